// round 1
// baseline (speedup 1.0000x reference)
#include <cuda_runtime.h>
#include <math.h>

// ---------------- problem constants ----------------
#define B_  32
#define C_  64
#define D_  128
#define HID 256
#define HW_ 64          // spatial H = W = 64
#define NPIX 4096       // 64*64
#define TOT1 36864      // C*C*9
#define NSTEP 32

// ---------------- device scratch (no allocations allowed) ----------------
__device__ float g_h2[B_][HID];
__device__ float g_film[4][B_][C_];           // g1, be1, g2, be2
__device__ float g_wpack[2][B_][9 * C_ * C_]; // [which][b][(tap*64+ci)*64+co]
__device__ float g_X[(size_t)B_ * C_ * NPIX]; // grid, NCHW
__device__ float g_U[(size_t)B_ * C_ * NPIX]; // intermediate, NCHW

// ---------------- hypernet small MLPs + FiLM heads ----------------
__global__ void hyper_small(const int* __restrict__ labels,
                            const float* __restrict__ emb,
                            const float* __restrict__ hw1, const float* __restrict__ hb1,
                            const float* __restrict__ hw2, const float* __restrict__ hb2,
                            const float* __restrict__ f1w1, const float* __restrict__ f1b1,
                            const float* __restrict__ f1w2, const float* __restrict__ f1b2,
                            const float* __restrict__ f2w1, const float* __restrict__ f2b1,
                            const float* __restrict__ f2w2, const float* __restrict__ f2b2)
{
    int b = blockIdx.x;
    int t = threadIdx.x;            // 256 threads
    __shared__ float s_cond[D_];
    __shared__ float s_h1[HID];
    __shared__ float s_t[D_];

    if (t < D_) s_cond[t] = emb[(size_t)labels[b] * D_ + t];
    __syncthreads();

    // h1 = relu(cond @ hw1 + hb1)  [256]
    {
        float a = hb1[t];
        #pragma unroll 4
        for (int k = 0; k < D_; k++) a = fmaf(s_cond[k], hw1[k * HID + t], a);
        s_h1[t] = fmaxf(a, 0.f);
    }
    __syncthreads();

    // h2 = relu(h1 @ hw2 + hb2)   [256]
    {
        float a = hb2[t];
        #pragma unroll 4
        for (int k = 0; k < HID; k++) a = fmaf(s_h1[k], hw2[k * HID + t], a);
        g_h2[b][t] = fmaxf(a, 0.f);
    }

    // FiLM 1
    if (t < D_) {
        float v = f1b1[t];
        #pragma unroll 4
        for (int k = 0; k < D_; k++) v = fmaf(s_cond[k], f1w1[k * D_ + t], v);
        s_t[t] = fmaxf(v, 0.f);
    }
    __syncthreads();
    if (t < D_) {
        float v = f1b2[t];
        #pragma unroll 4
        for (int k = 0; k < D_; k++) v = fmaf(s_t[k], f1w2[k * D_ + t], v);
        if (t < C_) g_film[0][b][t] = v; else g_film[1][b][t - C_] = v;
    }
    __syncthreads();

    // FiLM 2
    if (t < D_) {
        float v = f2b1[t];
        #pragma unroll 4
        for (int k = 0; k < D_; k++) v = fmaf(s_cond[k], f2w1[k * D_ + t], v);
        s_t[t] = fmaxf(v, 0.f);
    }
    __syncthreads();
    if (t < D_) {
        float v = f2b2[t];
        #pragma unroll 4
        for (int k = 0; k < D_; k++) v = fmaf(s_t[k], f2w2[k * D_ + t], v);
        if (t < C_) g_film[2][b][t] = v; else g_film[3][b][t - C_] = v;
    }
}

// ---------------- big hypernet layer: weights = h2 @ hw3 + hb3, repacked ----------------
// One block handles 256 consecutive j (columns of hw3) for ALL 32 samples.
__global__ void pack_weights(const float* __restrict__ hw3, const float* __restrict__ hb3)
{
    __shared__ float s_h2t[HID][B_];   // transposed: [k][b], 32KB
    int tid = threadIdx.x;
    for (int it = 0; it < B_; it++)
        s_h2t[tid][it] = g_h2[it][tid];   // coalesced read of g_h2[it][tid]
    __syncthreads();

    size_t j = (size_t)blockIdx.x * 256 + tid;   // j < 147456
    float acc[B_];
    #pragma unroll
    for (int b = 0; b < B_; b++) acc[b] = 0.f;

    const float* col = hw3 + j;
    #pragma unroll 4
    for (int k = 0; k < HID; k++) {
        float w = col[(size_t)k * (2 * TOT1)];
        const float4* v = reinterpret_cast<const float4*>(&s_h2t[k][0]);
        #pragma unroll
        for (int q = 0; q < 8; q++) {
            float4 h = v[q];
            acc[4 * q + 0] = fmaf(w, h.x, acc[4 * q + 0]);
            acc[4 * q + 1] = fmaf(w, h.y, acc[4 * q + 1]);
            acc[4 * q + 2] = fmaf(w, h.z, acc[4 * q + 2]);
            acc[4 * q + 3] = fmaf(w, h.w, acc[4 * q + 3]);
        }
    }

    float bias = hb3[j];
    int which = (j >= TOT1) ? 1 : 0;
    int jj = which ? (int)j - TOT1 : (int)j;
    int co  = jj / 576;
    int rem = jj - co * 576;
    int ci  = rem / 9;
    int tap = rem - ci * 9;
    int didx = (tap * C_ + ci) * C_ + co;
    #pragma unroll
    for (int b = 0; b < B_; b++)
        g_wpack[which][b][didx] = acc[b] + bias;
}

// ---------------- conv step: dynamic-weight 3x3 circular conv + FiLM (+ blend/rgb for B) ----------
// block = (ytile 0..15, b 0..31), 256 threads.
// thread tile: 8 pixels (p = lane + 32*i) x 8 output channels (co = (tid>>5)*8 + j)
__global__ __launch_bounds__(256, 2)
void conv_step(const float* __restrict__ init,
               const float* __restrict__ blendp,
               float* __restrict__ head,
               float* __restrict__ traj,
               int step, int isB)
{
    __shared__ float s_in[8][6][64];   // [ci][row][x]   12 KB
    __shared__ float s_w[9][8][64];    // [tap][ci][co]  18 KB

    const int tid  = threadIdx.x;
    const int lane = tid & 31;
    const int wgrp = tid >> 5;         // 8 co-groups
    const int co0  = wgrp * 8;
    const int yt   = blockIdx.x;       // 16 tiles of 4 rows
    const int b    = blockIdx.y;
    const int y0   = yt * 4;

    const float* in   = isB ? g_U : (step == 0 ? init : g_X);
    const float* bsrc = (step == 0) ? init : g_X;
    float* outbuf     = isB ? g_X : g_U;
    const float* wpk  = &g_wpack[isB][b][0];

    float acc[8][8];
    #pragma unroll
    for (int i = 0; i < 8; i++)
        #pragma unroll
        for (int j = 0; j < 8; j++) acc[i][j] = 0.f;

    for (int cb = 0; cb < C_; cb += 8) {
        // load input tile: 8 ci x 6 rows (y0-1 .. y0+4, wrapped) x 64 x
        #pragma unroll
        for (int it = 0; it < 12; it++) {
            int idx = tid + 256 * it;        // < 3072
            int x   = idx & 63;
            int row = (idx >> 6) % 6;
            int ci  = idx / 384;
            int gy  = (y0 - 1 + row + HW_) & (HW_ - 1);
            s_in[ci][row][x] = in[((size_t)(b * C_ + cb + ci)) * NPIX + gy * HW_ + x];
        }
        // load weight tile: 9 taps x 8 ci x 64 co
        #pragma unroll
        for (int it = 0; it < 18; it++) {
            int idx = tid + 256 * it;        // < 4608
            int co  = idx & 63;
            int ci  = (idx >> 6) & 7;
            int tap = idx / 512;
            s_w[tap][ci][co] = wpk[(tap * C_ + cb + ci) * C_ + co];
        }
        __syncthreads();

        #pragma unroll 1
        for (int tap = 0; tap < 9; tap++) {
            const int dy = tap / 3, dx = tap % 3;
            int off[8];
            #pragma unroll
            for (int i = 0; i < 8; i++) {
                int py = i >> 1;
                int px = lane + 32 * (i & 1);
                off[i] = (py + dy) * 64 + ((px + dx + 63) & 63);
            }
            const float* sbase = &s_in[0][0][0];
            #pragma unroll
            for (int ci = 0; ci < 8; ci++) {
                float4 bwa = *reinterpret_cast<const float4*>(&s_w[tap][ci][co0]);
                float4 bwb = *reinterpret_cast<const float4*>(&s_w[tap][ci][co0 + 4]);
                const float* srow = sbase + ci * 384;
                #pragma unroll
                for (int i = 0; i < 8; i++) {
                    float av = srow[off[i]];
                    acc[i][0] = fmaf(av, bwa.x, acc[i][0]);
                    acc[i][1] = fmaf(av, bwa.y, acc[i][1]);
                    acc[i][2] = fmaf(av, bwa.z, acc[i][2]);
                    acc[i][3] = fmaf(av, bwa.w, acc[i][3]);
                    acc[i][4] = fmaf(av, bwb.x, acc[i][4]);
                    acc[i][5] = fmaf(av, bwb.y, acc[i][5]);
                    acc[i][6] = fmaf(av, bwb.z, acc[i][6]);
                    acc[i][7] = fmaf(av, bwb.w, acc[i][7]);
                }
            }
        }
        __syncthreads();
    }

    // epilogue: FiLM + relu (+ blend + rgb for pass B)
    float gv[8], bv[8];
    #pragma unroll
    for (int j = 0; j < 8; j++) {
        gv[j] = g_film[isB * 2][b][co0 + j];
        bv[j] = g_film[isB * 2 + 1][b][co0 + j];
    }
    float s = 0.f, oms = 1.f;
    if (isB) {
        s = 1.f / (1.f + expf(-blendp[0]));
        oms = 1.f - s;
    }

    #pragma unroll
    for (int i = 0; i < 8; i++) {
        int py = i >> 1;
        int px = lane + 32 * (i & 1);
        int y = y0 + py;
        #pragma unroll
        for (int j = 0; j < 8; j++) {
            int co = co0 + j;
            float v = fmaxf(fmaf(gv[j], acc[i][j], bv[j]), 0.f);
            size_t o = ((size_t)(b * C_ + co)) * NPIX + (size_t)y * HW_ + px;
            if (!isB) {
                outbuf[o] = v;
            } else {
                float ng = fmaf(oms, bsrc[o], s * v);
                outbuf[o] = ng;
                if (co < 3) {
                    float r = 1.f / (1.f + expf(-ng));
                    traj[(((size_t)step * B_ + b) * 3 + co) * NPIX + (size_t)y * HW_ + px] = r;
                    if (step == NSTEP - 1)
                        head[((size_t)(b * 3 + co)) * NPIX + (size_t)y * HW_ + px] = r;
                }
            }
        }
    }
}

// ---------------- launcher ----------------
extern "C" void kernel_launch(void* const* d_in, const int* in_sizes, int n_in,
                              void* d_out, int out_size)
{
    const int*   labels = (const int*)  d_in[0];
    const float* init   = (const float*)d_in[1];
    const float* emb    = (const float*)d_in[2];
    const float* hw1    = (const float*)d_in[3];
    const float* hb1    = (const float*)d_in[4];
    const float* hw2    = (const float*)d_in[5];
    const float* hb2    = (const float*)d_in[6];
    const float* hw3    = (const float*)d_in[7];
    const float* hb3    = (const float*)d_in[8];
    const float* f1w1   = (const float*)d_in[9];
    const float* f1b1   = (const float*)d_in[10];
    const float* f1w2   = (const float*)d_in[11];
    const float* f1b2   = (const float*)d_in[12];
    const float* f2w1   = (const float*)d_in[13];
    const float* f2b1   = (const float*)d_in[14];
    const float* f2w2   = (const float*)d_in[15];
    const float* f2b2   = (const float*)d_in[16];
    const float* blend  = (const float*)d_in[17];

    float* out  = (float*)d_out;
    float* head = out;                              // traj[-1]: [B,3,H,W]
    float* traj = out + (size_t)B_ * 3 * NPIX;      // traj:     [T,B,3,H,W]

    hyper_small<<<B_, 256>>>(labels, emb, hw1, hb1, hw2, hb2,
                             f1w1, f1b1, f1w2, f1b2, f2w1, f2b1, f2w2, f2b2);
    pack_weights<<<(2 * TOT1) / 256, 256>>>(hw3, hb3);

    for (int t = 0; t < NSTEP; t++) {
        conv_step<<<dim3(16, B_), 256>>>(init, blend, head, traj, t, 0);
        conv_step<<<dim3(16, B_), 256>>>(init, blend, head, traj, t, 1);
    }
}

// round 2
// speedup vs baseline: 1.0160x; 1.0160x over previous
#include <cuda_runtime.h>
#include <math.h>

// ---------------- problem constants ----------------
#define B_  32
#define C_  64
#define D_  128
#define HID 256
#define HW_ 64          // spatial H = W = 64
#define NPIX 4096       // 64*64
#define TOT1 36864      // C*C*9
#define NSTEP 32

typedef unsigned long long u64;

// ---------------- device scratch (no allocations allowed) ----------------
__device__ float g_h2[B_][HID];
__device__ float g_film[4][B_][C_];            // g1, be1, g2, be2
// packed weights, ci-pair interleaved:
// index = ((tap*32 + (ci>>1))*64 + co)*2 + (ci&1)
__device__ float g_wpack[2][B_][9 * 32 * C_ * 2];
__device__ float g_X[(size_t)B_ * C_ * NPIX];  // grid, NCHW
__device__ float g_U[(size_t)B_ * C_ * NPIX];  // intermediate, NCHW

// packed dual-fp32 FMA: d.lo += a.lo*b.lo ; d.hi += a.hi*b.hi  (FFMA2 in SASS)
__device__ __forceinline__ void ffma2(u64& d, u64 a, u64 b) {
    asm("fma.rn.f32x2 %0, %1, %2, %0;" : "+l"(d) : "l"(a), "l"(b));
}

// ---------------- hypernet small MLPs + FiLM heads ----------------
__global__ void hyper_small(const int* __restrict__ labels,
                            const float* __restrict__ emb,
                            const float* __restrict__ hw1, const float* __restrict__ hb1,
                            const float* __restrict__ hw2, const float* __restrict__ hb2,
                            const float* __restrict__ f1w1, const float* __restrict__ f1b1,
                            const float* __restrict__ f1w2, const float* __restrict__ f1b2,
                            const float* __restrict__ f2w1, const float* __restrict__ f2b1,
                            const float* __restrict__ f2w2, const float* __restrict__ f2b2)
{
    int b = blockIdx.x;
    int t = threadIdx.x;            // 256 threads
    __shared__ float s_cond[D_];
    __shared__ float s_h1[HID];
    __shared__ float s_t[D_];

    if (t < D_) s_cond[t] = emb[(size_t)labels[b] * D_ + t];
    __syncthreads();

    {
        float a = hb1[t];
        #pragma unroll 4
        for (int k = 0; k < D_; k++) a = fmaf(s_cond[k], hw1[k * HID + t], a);
        s_h1[t] = fmaxf(a, 0.f);
    }
    __syncthreads();

    {
        float a = hb2[t];
        #pragma unroll 4
        for (int k = 0; k < HID; k++) a = fmaf(s_h1[k], hw2[k * HID + t], a);
        g_h2[b][t] = fmaxf(a, 0.f);
    }

    if (t < D_) {
        float v = f1b1[t];
        #pragma unroll 4
        for (int k = 0; k < D_; k++) v = fmaf(s_cond[k], f1w1[k * D_ + t], v);
        s_t[t] = fmaxf(v, 0.f);
    }
    __syncthreads();
    if (t < D_) {
        float v = f1b2[t];
        #pragma unroll 4
        for (int k = 0; k < D_; k++) v = fmaf(s_t[k], f1w2[k * D_ + t], v);
        if (t < C_) g_film[0][b][t] = v; else g_film[1][b][t - C_] = v;
    }
    __syncthreads();

    if (t < D_) {
        float v = f2b1[t];
        #pragma unroll 4
        for (int k = 0; k < D_; k++) v = fmaf(s_cond[k], f2w1[k * D_ + t], v);
        s_t[t] = fmaxf(v, 0.f);
    }
    __syncthreads();
    if (t < D_) {
        float v = f2b2[t];
        #pragma unroll 4
        for (int k = 0; k < D_; k++) v = fmaf(s_t[k], f2w2[k * D_ + t], v);
        if (t < C_) g_film[2][b][t] = v; else g_film[3][b][t - C_] = v;
    }
}

// ---------------- big hypernet layer: weights = h2 @ hw3 + hb3, repacked ----------------
__global__ void pack_weights(const float* __restrict__ hw3, const float* __restrict__ hb3)
{
    __shared__ float s_h2t[HID][B_];
    int tid = threadIdx.x;
    for (int it = 0; it < B_; it++)
        s_h2t[tid][it] = g_h2[it][tid];
    __syncthreads();

    size_t j = (size_t)blockIdx.x * 256 + tid;   // j < 147456
    float acc[B_];
    #pragma unroll
    for (int b = 0; b < B_; b++) acc[b] = 0.f;

    const float* col = hw3 + j;
    #pragma unroll 4
    for (int k = 0; k < HID; k++) {
        float w = col[(size_t)k * (2 * TOT1)];
        const float4* v = reinterpret_cast<const float4*>(&s_h2t[k][0]);
        #pragma unroll
        for (int q = 0; q < 8; q++) {
            float4 h = v[q];
            acc[4 * q + 0] = fmaf(w, h.x, acc[4 * q + 0]);
            acc[4 * q + 1] = fmaf(w, h.y, acc[4 * q + 1]);
            acc[4 * q + 2] = fmaf(w, h.z, acc[4 * q + 2]);
            acc[4 * q + 3] = fmaf(w, h.w, acc[4 * q + 3]);
        }
    }

    float bias = hb3[j];
    int which = (j >= TOT1) ? 1 : 0;
    int jj = which ? (int)j - TOT1 : (int)j;
    int co  = jj / 576;
    int rem = jj - co * 576;
    int ci  = rem / 9;
    int tap = rem - ci * 9;
    // ci-pair interleaved layout
    int didx = ((tap * 32 + (ci >> 1)) * C_ + co) * 2 + (ci & 1);
    #pragma unroll
    for (int b = 0; b < B_; b++)
        g_wpack[which][b][didx] = acc[b] + bias;
}

// ---------------- conv step with FFMA2 (f32x2) ----------------
// block = (ytile 0..31, b 0..31), 256 threads, 2-row output tiles.
// thread: 4 pixels (row=i>>1, px=lane+32*(i&1)) x 8 output channels (co=(tid>>5)*8+j)
// f32x2 lanes hold even/odd-ci partial sums; summed in epilogue.
__global__ __launch_bounds__(256, 2)
void conv_step(const float* __restrict__ init,
               const float* __restrict__ blendp,
               float* __restrict__ head,
               float* __restrict__ traj,
               int step, int isB)
{
    // [cp][row(4)][x(64)][pair(2)]  = 2048 floats (8 KB)
    __shared__ __align__(16) float s_in[4 * 4 * 64 * 2];
    // [tap(9)][cp(4)][co(64)][pair(2)] = 4608 floats (18 KB)
    __shared__ __align__(16) float s_w[9 * 4 * 64 * 2];

    const int tid  = threadIdx.x;
    const int lane = tid & 31;
    const int wgrp = tid >> 5;         // 8 co-groups of 8
    const int co0  = wgrp * 8;
    const int yt   = blockIdx.x;       // 32 tiles of 2 rows
    const int b    = blockIdx.y;
    const int y0   = yt * 2;

    const float* in   = isB ? g_U : (step == 0 ? init : g_X);
    const float* bsrc = (step == 0) ? init : g_X;
    float* outbuf     = isB ? g_X : g_U;
    const float* wpk  = &g_wpack[isB][b][0];

    u64 acc[4][8];
    #pragma unroll
    for (int i = 0; i < 4; i++)
        #pragma unroll
        for (int j = 0; j < 8; j++) acc[i][j] = 0ULL;

    for (int cb = 0; cb < C_; cb += 8) {
        // input tile: 8 ci (4 pairs) x 4 rows (y0-1..y0+2 wrapped) x 64 x
        #pragma unroll
        for (int it = 0; it < 8; it++) {
            int idx = tid + 256 * it;          // < 2048
            int x   = idx & 63;
            int row = (idx >> 6) & 3;
            int ci  = idx >> 8;                // 0..7
            int gy  = (y0 - 1 + row + HW_) & (HW_ - 1);
            s_in[(((ci >> 1) * 4 + row) * 64 + x) * 2 + (ci & 1)] =
                in[((size_t)(b * C_ + cb + ci)) * NPIX + gy * HW_ + x];
        }
        // weight tile: 9 taps x 4 ci-pairs x 64 co x 2 (contiguous 128-float rows)
        #pragma unroll
        for (int it = 0; it < 18; it++) {
            int idx = tid + 256 * it;          // < 4608
            int c2  = idx & 127;
            int cp  = (idx >> 7) & 3;
            int tap = idx >> 9;                // 0..8
            s_w[(tap * 4 + cp) * 128 + c2] =
                wpk[((tap * 32 + (cb >> 1) + cp) * C_) * 2 + c2];
        }
        __syncthreads();

        #pragma unroll 1
        for (int tap = 0; tap < 9; tap++) {
            const int dy = tap / 3, dx = tap % 3;
            int off[4];
            #pragma unroll
            for (int i = 0; i < 4; i++) {
                int py = i >> 1;
                int px = lane + 32 * (i & 1);
                off[i] = (py + dy) * 64 + ((px + dx + 63) & 63);
            }
            #pragma unroll
            for (int cp = 0; cp < 4; cp++) {
                const u64* ibase = reinterpret_cast<const u64*>(s_in) + cp * 256;
                const ulonglong2* wb =
                    reinterpret_cast<const ulonglong2*>(s_w + (tap * 4 + cp) * 128 + co0 * 2);
                ulonglong2 wA = wb[0];
                ulonglong2 wB = wb[1];
                ulonglong2 wC = wb[2];
                ulonglong2 wD = wb[3];
                u64 a0 = ibase[off[0]];
                u64 a1 = ibase[off[1]];
                u64 a2 = ibase[off[2]];
                u64 a3 = ibase[off[3]];

                ffma2(acc[0][0], a0, wA.x); ffma2(acc[0][1], a0, wA.y);
                ffma2(acc[0][2], a0, wB.x); ffma2(acc[0][3], a0, wB.y);
                ffma2(acc[0][4], a0, wC.x); ffma2(acc[0][5], a0, wC.y);
                ffma2(acc[0][6], a0, wD.x); ffma2(acc[0][7], a0, wD.y);

                ffma2(acc[1][0], a1, wA.x); ffma2(acc[1][1], a1, wA.y);
                ffma2(acc[1][2], a1, wB.x); ffma2(acc[1][3], a1, wB.y);
                ffma2(acc[1][4], a1, wC.x); ffma2(acc[1][5], a1, wC.y);
                ffma2(acc[1][6], a1, wD.x); ffma2(acc[1][7], a1, wD.y);

                ffma2(acc[2][0], a2, wA.x); ffma2(acc[2][1], a2, wA.y);
                ffma2(acc[2][2], a2, wB.x); ffma2(acc[2][3], a2, wB.y);
                ffma2(acc[2][4], a2, wC.x); ffma2(acc[2][5], a2, wC.y);
                ffma2(acc[2][6], a2, wD.x); ffma2(acc[2][7], a2, wD.y);

                ffma2(acc[3][0], a3, wA.x); ffma2(acc[3][1], a3, wA.y);
                ffma2(acc[3][2], a3, wB.x); ffma2(acc[3][3], a3, wB.y);
                ffma2(acc[3][4], a3, wC.x); ffma2(acc[3][5], a3, wC.y);
                ffma2(acc[3][6], a3, wD.x); ffma2(acc[3][7], a3, wD.y);
            }
        }
        __syncthreads();
    }

    // epilogue: FiLM + relu (+ blend + rgb for pass B)
    float gv[8], bv[8];
    #pragma unroll
    for (int j = 0; j < 8; j++) {
        gv[j] = g_film[isB * 2][b][co0 + j];
        bv[j] = g_film[isB * 2 + 1][b][co0 + j];
    }
    float s = 0.f, oms = 1.f;
    if (isB) {
        s = 1.f / (1.f + expf(-blendp[0]));
        oms = 1.f - s;
    }

    #pragma unroll
    for (int i = 0; i < 4; i++) {
        int py = i >> 1;
        int px = lane + 32 * (i & 1);
        int y = y0 + py;
        #pragma unroll
        for (int j = 0; j < 8; j++) {
            int co = co0 + j;
            float2 p = *reinterpret_cast<float2*>(&acc[i][j]);
            float conv = p.x + p.y;
            float v = fmaxf(fmaf(gv[j], conv, bv[j]), 0.f);
            size_t o = ((size_t)(b * C_ + co)) * NPIX + (size_t)y * HW_ + px;
            if (!isB) {
                outbuf[o] = v;
            } else {
                float ng = fmaf(oms, bsrc[o], s * v);
                outbuf[o] = ng;
                if (co < 3) {
                    float r = 1.f / (1.f + expf(-ng));
                    traj[(((size_t)step * B_ + b) * 3 + co) * NPIX + (size_t)y * HW_ + px] = r;
                    if (step == NSTEP - 1)
                        head[((size_t)(b * 3 + co)) * NPIX + (size_t)y * HW_ + px] = r;
                }
            }
        }
    }
}

// ---------------- launcher ----------------
extern "C" void kernel_launch(void* const* d_in, const int* in_sizes, int n_in,
                              void* d_out, int out_size)
{
    const int*   labels = (const int*)  d_in[0];
    const float* init   = (const float*)d_in[1];
    const float* emb    = (const float*)d_in[2];
    const float* hw1    = (const float*)d_in[3];
    const float* hb1    = (const float*)d_in[4];
    const float* hw2    = (const float*)d_in[5];
    const float* hb2    = (const float*)d_in[6];
    const float* hw3    = (const float*)d_in[7];
    const float* hb3    = (const float*)d_in[8];
    const float* f1w1   = (const float*)d_in[9];
    const float* f1b1   = (const float*)d_in[10];
    const float* f1w2   = (const float*)d_in[11];
    const float* f1b2   = (const float*)d_in[12];
    const float* f2w1   = (const float*)d_in[13];
    const float* f2b1   = (const float*)d_in[14];
    const float* f2w2   = (const float*)d_in[15];
    const float* f2b2   = (const float*)d_in[16];
    const float* blend  = (const float*)d_in[17];

    float* out  = (float*)d_out;
    float* head = out;                              // traj[-1]: [B,3,H,W]
    float* traj = out + (size_t)B_ * 3 * NPIX;      // traj:     [T,B,3,H,W]

    hyper_small<<<B_, 256>>>(labels, emb, hw1, hb1, hw2, hb2,
                             f1w1, f1b1, f1w2, f1b2, f2w1, f2b1, f2w2, f2b2);
    pack_weights<<<(2 * TOT1) / 256, 256>>>(hw3, hb3);

    for (int t = 0; t < NSTEP; t++) {
        conv_step<<<dim3(32, B_), 256>>>(init, blend, head, traj, t, 0);
        conv_step<<<dim3(32, B_), 256>>>(init, blend, head, traj, t, 1);
    }
}

// round 3
// speedup vs baseline: 1.4513x; 1.4284x over previous
#include <cuda_runtime.h>
#include <cuda_bf16.h>
#include <math.h>

// ---------------- problem constants ----------------
#define B_  32
#define C_  64
#define D_  128
#define HID 256
#define HW_ 64          // spatial H = W = 64
#define NPIX 4096       // 64*64
#define TOT1 36864      // C*C*9
#define NSTEP 32

// ---------------- device scratch ----------------
__device__ float g_h2[B_][HID];
__device__ float g_film[4][B_][C_];   // g1, be1, g2, be2
// bf16 hi/lo weight planes: [which][b][cc(4)][tap(9)][co(64)][ci16]
__device__ __nv_bfloat16 g_wh[2][B_][4 * 9 * C_ * 16];
__device__ __nv_bfloat16 g_wl[2][B_][4 * 9 * C_ * 16];
__device__ float g_X[(size_t)B_ * C_ * NPIX];  // grid, NCHW f32
__device__ float g_U[(size_t)B_ * C_ * NPIX];  // intermediate, NCHW f32

// ---------------- PTX helpers ----------------
__device__ __forceinline__ unsigned smem_u32(const void* p) {
    return (unsigned)__cvta_generic_to_shared(p);
}
__device__ __forceinline__ void ldsm4(unsigned* r, unsigned addr) {
    asm volatile("ldmatrix.sync.aligned.m8n8.x4.shared.b16 {%0,%1,%2,%3}, [%4];"
        : "=r"(r[0]), "=r"(r[1]), "=r"(r[2]), "=r"(r[3]) : "r"(addr));
}
__device__ __forceinline__ void mma16816(float* d, const unsigned* a,
                                         unsigned b0, unsigned b1) {
    asm volatile("mma.sync.aligned.m16n8k16.row.col.f32.bf16.bf16.f32 "
                 "{%0,%1,%2,%3}, {%4,%5,%6,%7}, {%8,%9}, {%0,%1,%2,%3};"
        : "+f"(d[0]), "+f"(d[1]), "+f"(d[2]), "+f"(d[3])
        : "r"(a[0]), "r"(a[1]), "r"(a[2]), "r"(a[3]), "r"(b0), "r"(b1));
}

// ---------------- hypernet small MLPs + FiLM heads ----------------
__global__ void hyper_small(const int* __restrict__ labels,
                            const float* __restrict__ emb,
                            const float* __restrict__ hw1, const float* __restrict__ hb1,
                            const float* __restrict__ hw2, const float* __restrict__ hb2,
                            const float* __restrict__ f1w1, const float* __restrict__ f1b1,
                            const float* __restrict__ f1w2, const float* __restrict__ f1b2,
                            const float* __restrict__ f2w1, const float* __restrict__ f2b1,
                            const float* __restrict__ f2w2, const float* __restrict__ f2b2)
{
    int b = blockIdx.x;
    int t = threadIdx.x;            // 256 threads
    __shared__ float s_cond[D_];
    __shared__ float s_h1[HID];
    __shared__ float s_t[D_];

    if (t < D_) s_cond[t] = emb[(size_t)labels[b] * D_ + t];
    __syncthreads();

    {
        float a = hb1[t];
        #pragma unroll 4
        for (int k = 0; k < D_; k++) a = fmaf(s_cond[k], hw1[k * HID + t], a);
        s_h1[t] = fmaxf(a, 0.f);
    }
    __syncthreads();

    {
        float a = hb2[t];
        #pragma unroll 4
        for (int k = 0; k < HID; k++) a = fmaf(s_h1[k], hw2[k * HID + t], a);
        g_h2[b][t] = fmaxf(a, 0.f);
    }

    if (t < D_) {
        float v = f1b1[t];
        #pragma unroll 4
        for (int k = 0; k < D_; k++) v = fmaf(s_cond[k], f1w1[k * D_ + t], v);
        s_t[t] = fmaxf(v, 0.f);
    }
    __syncthreads();
    if (t < D_) {
        float v = f1b2[t];
        #pragma unroll 4
        for (int k = 0; k < D_; k++) v = fmaf(s_t[k], f1w2[k * D_ + t], v);
        if (t < C_) g_film[0][b][t] = v; else g_film[1][b][t - C_] = v;
    }
    __syncthreads();

    if (t < D_) {
        float v = f2b1[t];
        #pragma unroll 4
        for (int k = 0; k < D_; k++) v = fmaf(s_cond[k], f2w1[k * D_ + t], v);
        s_t[t] = fmaxf(v, 0.f);
    }
    __syncthreads();
    if (t < D_) {
        float v = f2b2[t];
        #pragma unroll 4
        for (int k = 0; k < D_; k++) v = fmaf(s_t[k], f2w2[k * D_ + t], v);
        if (t < C_) g_film[2][b][t] = v; else g_film[3][b][t - C_] = v;
    }
}

// ---------------- big hypernet layer -> bf16 hi/lo planes ----------------
__global__ void pack_weights(const float* __restrict__ hw3, const float* __restrict__ hb3)
{
    __shared__ float s_h2t[HID][B_];
    int tid = threadIdx.x;
    for (int it = 0; it < B_; it++)
        s_h2t[tid][it] = g_h2[it][tid];
    __syncthreads();

    size_t j = (size_t)blockIdx.x * 256 + tid;   // j < 147456
    float acc[B_];
    #pragma unroll
    for (int b = 0; b < B_; b++) acc[b] = 0.f;

    const float* col = hw3 + j;
    #pragma unroll 4
    for (int k = 0; k < HID; k++) {
        float w = col[(size_t)k * (2 * TOT1)];
        const float4* v = reinterpret_cast<const float4*>(&s_h2t[k][0]);
        #pragma unroll
        for (int q = 0; q < 8; q++) {
            float4 h = v[q];
            acc[4 * q + 0] = fmaf(w, h.x, acc[4 * q + 0]);
            acc[4 * q + 1] = fmaf(w, h.y, acc[4 * q + 1]);
            acc[4 * q + 2] = fmaf(w, h.z, acc[4 * q + 2]);
            acc[4 * q + 3] = fmaf(w, h.w, acc[4 * q + 3]);
        }
    }

    float bias = hb3[j];
    int which = (j >= TOT1) ? 1 : 0;
    int jj = which ? (int)j - TOT1 : (int)j;
    int co  = jj / 576;
    int rem = jj - co * 576;
    int ci  = rem / 9;
    int tap = rem - ci * 9;
    int cc  = ci >> 4;
    int cl  = ci & 15;
    int didx = ((cc * 9 + tap) * C_ + co) * 16 + cl;
    #pragma unroll
    for (int b = 0; b < B_; b++) {
        float v = acc[b] + bias;
        __nv_bfloat16 h = __float2bfloat16(v);
        __nv_bfloat16 l = __float2bfloat16(v - __bfloat162float(h));
        g_wh[which][b][didx] = h;
        g_wl[which][b][didx] = l;
    }
}

// ---------------- conv step via bf16x3 tensor-core implicit GEMM ----------------
// block: (ytile 0..31, b 0..31), 256 threads = 8 warps.
// Output tile: 128 pixels (2 rows x 64) x 64 co.
// warp (wm 0..3, wn 0..1): m32 (wm) x n32 (wn); 2 m16-tiles x 4 n8-tiles.
// smem A: [row 4][slot 66][pitch 24 bf16], hi & lo planes. slot j = global x (j-1)&63.
// smem B: [tap 9][co 64][pitch 24 bf16], hi & lo planes.
#define SIN_PLANE (4 * 66 * 24)   // bf16 elems per plane
#define SW_PLANE  (9 * 64 * 24)
#define SMEM_BYTES ((2 * SIN_PLANE + 2 * SW_PLANE) * 2)  // 80640 B

__global__ __launch_bounds__(256, 2)
void conv_step(const float* __restrict__ init,
               const float* __restrict__ blendp,
               float* __restrict__ head,
               float* __restrict__ traj,
               int step, int isB)
{
    extern __shared__ __align__(16) char smem[];
    __nv_bfloat16* s_inh = reinterpret_cast<__nv_bfloat16*>(smem);
    __nv_bfloat16* s_inl = s_inh + SIN_PLANE;
    __nv_bfloat16* s_wh  = s_inl + SIN_PLANE;
    __nv_bfloat16* s_wl  = s_wh + SW_PLANE;

    const int tid  = threadIdx.x;
    const int lane = tid & 31;
    const int wid  = tid >> 5;
    const int wm   = wid & 3;          // m-group (pixels)
    const int wn   = wid >> 2;         // n-group (co)
    const int b    = blockIdx.y;
    const int y0   = blockIdx.x * 2;

    const float* in   = isB ? g_U : (step == 0 ? init : g_X);
    const float* bsrc = (step == 0) ? init : g_X;
    float* outbuf     = isB ? g_X : g_U;
    const __nv_bfloat16* wbh = &g_wh[isB][b][0];
    const __nv_bfloat16* wbl = &g_wl[isB][b][0];

    const unsigned u_inh = smem_u32(s_inh);
    const unsigned u_inl = smem_u32(s_inl);
    const unsigned u_wh  = smem_u32(s_wh);
    const unsigned u_wl  = smem_u32(s_wl);

    // per-lane ldmatrix base offsets (bytes), tap offset added later
    const int g  = lane >> 3;
    const int r8 = lane & 7;
    const int yl = wm >> 1;
    const int xb = (wm & 1) * 32;
    unsigned aoff[2], boff[2];
    #pragma unroll
    for (int t = 0; t < 2; t++)
        aoff[t] = (unsigned)((yl * 66 + xb + t * 16 + (g & 1) * 8 + r8) * 48 + (g >> 1) * 16);
    #pragma unroll
    for (int p = 0; p < 2; p++)
        boff[p] = (unsigned)((wn * 32 + p * 16 + (g >> 1) * 8 + r8) * 48 + (g & 1) * 16);

    float acc[2][4][4];
    #pragma unroll
    for (int t = 0; t < 2; t++)
        #pragma unroll
        for (int n = 0; n < 4; n++)
            #pragma unroll
            for (int k = 0; k < 4; k++) acc[t][n][k] = 0.f;

    for (int cc = 0; cc < 4; cc++) {
        // ---- input tile: 4 rows x 66 slots x 16 ci, f32 -> bf16 hi/lo ----
        #pragma unroll 4
        for (int it = 0; it < 17; it++) {
            int idx = tid + 256 * it;          // < 4224
            if (idx < 4224) {
                int j   = idx % 66;
                int q   = idx / 66;
                int ci  = q & 15;
                int row = q >> 4;
                int gy  = (y0 - 1 + row) & 63;
                int gx  = (j + 63) & 63;
                float v = in[((size_t)(b * C_ + cc * 16 + ci)) * NPIX + gy * HW_ + gx];
                __nv_bfloat16 h = __float2bfloat16(v);
                __nv_bfloat16 l = __float2bfloat16(v - __bfloat162float(h));
                int so = (row * 66 + j) * 24 + ci;
                s_inh[so] = h;
                s_inl[so] = l;
            }
        }
        // ---- weight tile: 9 taps x 64 co x 16 ci, both planes, 16B chunks ----
        {
            const uint4* g4h = reinterpret_cast<const uint4*>(wbh + cc * (9 * C_ * 16));
            const uint4* g4l = reinterpret_cast<const uint4*>(wbl + cc * (9 * C_ * 16));
            uint4* s4h = reinterpret_cast<uint4*>(s_wh);
            uint4* s4l = reinterpret_cast<uint4*>(s_wl);
            #pragma unroll
            for (int it = 0; it < 5; it++) {
                int idx = tid + 256 * it;       // < 1152
                if (idx < 1152) {
                    int ci8 = idx & 1;
                    int co  = (idx >> 1) & 63;
                    int tap = idx >> 7;
                    int so  = (tap * 64 + co) * 3 + ci8;   // uint4 units (24 bf16 = 3 x uint4)
                    s4h[so] = g4h[idx];
                    s4l[so] = g4l[idx];
                }
            }
        }
        __syncthreads();

        #pragma unroll
        for (int tap = 0; tap < 9; tap++) {
            const int dy = tap / 3, dx = tap % 3;
            const unsigned ta = (unsigned)((dy * 66 + dx) * 48);
            const unsigned tb = (unsigned)(tap * 64 * 48);

            unsigned ah[2][4], al[2][4], bh[2][4], bl[2][4];
            #pragma unroll
            for (int t = 0; t < 2; t++) {
                ldsm4(ah[t], u_inh + aoff[t] + ta);
                ldsm4(al[t], u_inl + aoff[t] + ta);
            }
            #pragma unroll
            for (int p = 0; p < 2; p++) {
                ldsm4(bh[p], u_wh + boff[p] + tb);
                ldsm4(bl[p], u_wl + boff[p] + tb);
            }
            #pragma unroll
            for (int t = 0; t < 2; t++) {
                #pragma unroll
                for (int p = 0; p < 2; p++) {
                    // hi*hi
                    mma16816(acc[t][2 * p],     ah[t], bh[p][0], bh[p][1]);
                    mma16816(acc[t][2 * p + 1], ah[t], bh[p][2], bh[p][3]);
                    // hi*lo
                    mma16816(acc[t][2 * p],     ah[t], bl[p][0], bl[p][1]);
                    mma16816(acc[t][2 * p + 1], ah[t], bl[p][2], bl[p][3]);
                    // lo*hi
                    mma16816(acc[t][2 * p],     al[t], bh[p][0], bh[p][1]);
                    mma16816(acc[t][2 * p + 1], al[t], bh[p][2], bh[p][3]);
                }
            }
        }
        __syncthreads();
    }

    // ---------------- epilogue ----------------
    float s = 0.f, oms = 1.f;
    if (isB) {
        s = 1.f / (1.f + expf(-blendp[0]));
        oms = 1.f - s;
    }
    const int y = y0 + yl;
    const int rbase = lane >> 2;
    const int cpair = (lane & 3) * 2;

    #pragma unroll
    for (int t = 0; t < 2; t++) {
        #pragma unroll
        for (int n = 0; n < 4; n++) {
            #pragma unroll
            for (int half = 0; half < 2; half++) {
                int px = xb + t * 16 + rbase + 8 * half;
                #pragma unroll
                for (int e = 0; e < 2; e++) {
                    int co = wn * 32 + n * 8 + cpair + e;
                    float conv = acc[t][n][2 * half + e];
                    float gv = g_film[isB * 2][b][co];
                    float bv = g_film[isB * 2 + 1][b][co];
                    float v = fmaxf(fmaf(gv, conv, bv), 0.f);
                    size_t o = ((size_t)(b * C_ + co)) * NPIX + (size_t)y * HW_ + px;
                    if (!isB) {
                        outbuf[o] = v;
                    } else {
                        float ng = fmaf(oms, bsrc[o], s * v);
                        outbuf[o] = ng;
                        if (co < 3) {
                            float r = 1.f / (1.f + expf(-ng));
                            traj[(((size_t)step * B_ + b) * 3 + co) * NPIX + (size_t)y * HW_ + px] = r;
                            if (step == NSTEP - 1)
                                head[((size_t)(b * 3 + co)) * NPIX + (size_t)y * HW_ + px] = r;
                        }
                    }
                }
            }
        }
    }
}

// ---------------- launcher ----------------
extern "C" void kernel_launch(void* const* d_in, const int* in_sizes, int n_in,
                              void* d_out, int out_size)
{
    const int*   labels = (const int*)  d_in[0];
    const float* init   = (const float*)d_in[1];
    const float* emb    = (const float*)d_in[2];
    const float* hw1    = (const float*)d_in[3];
    const float* hb1    = (const float*)d_in[4];
    const float* hw2    = (const float*)d_in[5];
    const float* hb2    = (const float*)d_in[6];
    const float* hw3    = (const float*)d_in[7];
    const float* hb3    = (const float*)d_in[8];
    const float* f1w1   = (const float*)d_in[9];
    const float* f1b1   = (const float*)d_in[10];
    const float* f1w2   = (const float*)d_in[11];
    const float* f1b2   = (const float*)d_in[12];
    const float* f2w1   = (const float*)d_in[13];
    const float* f2b1   = (const float*)d_in[14];
    const float* f2w2   = (const float*)d_in[15];
    const float* f2b2   = (const float*)d_in[16];
    const float* blend  = (const float*)d_in[17];

    float* out  = (float*)d_out;
    float* head = out;                              // traj[-1]: [B,3,H,W]
    float* traj = out + (size_t)B_ * 3 * NPIX;      // traj:     [T,B,3,H,W]

    static bool attr_set = false;
    cudaFuncSetAttribute(conv_step, cudaFuncAttributeMaxDynamicSharedMemorySize, SMEM_BYTES);
    (void)attr_set;

    hyper_small<<<B_, 256>>>(labels, emb, hw1, hb1, hw2, hb2,
                             f1w1, f1b1, f1w2, f1b2, f2w1, f2b1, f2w2, f2b2);
    pack_weights<<<(2 * TOT1) / 256, 256>>>(hw3, hb3);

    for (int t = 0; t < NSTEP; t++) {
        conv_step<<<dim3(32, B_), 256, SMEM_BYTES>>>(init, blend, head, traj, t, 0);
        conv_step<<<dim3(32, B_), 256, SMEM_BYTES>>>(init, blend, head, traj, t, 1);
    }
}

// round 4
// speedup vs baseline: 2.2748x; 1.5675x over previous
#include <cuda_runtime.h>
#include <cuda_bf16.h>
#include <math.h>

// ---------------- problem constants ----------------
#define B_  32
#define C_  64
#define D_  128
#define HID 256
#define HW_ 64
#define NPIX 4096
#define TOT1 36864
#define NSTEP 32

// ---------------- device scratch ----------------
__device__ float g_h2[B_][HID];
__device__ float g_film[4][B_][C_];   // g1, be1, g2, be2
// bf16 hi/lo weight planes: [which][b][cc(4)][tap(9)][co(64)][ci16]
__device__ __nv_bfloat16 g_wh[2][B_][4 * 9 * C_ * 16];
__device__ __nv_bfloat16 g_wl[2][B_][4 * 9 * C_ * 16];
// activation planes: [b][cc(4)][y][x][ci16]
__device__ __nv_bfloat16 g_sh[(size_t)B_ * 4 * NPIX * 16];  // state (hi)
__device__ __nv_bfloat16 g_sl[(size_t)B_ * 4 * NPIX * 16];  // state (lo)
__device__ __nv_bfloat16 g_uh[(size_t)B_ * 4 * NPIX * 16];  // intermediate (hi)
__device__ __nv_bfloat16 g_ul[(size_t)B_ * 4 * NPIX * 16];  // intermediate (lo)
__device__ float g_X[(size_t)B_ * C_ * NPIX];               // f32 state (blend source), NCHW

// ---------------- PTX helpers ----------------
__device__ __forceinline__ unsigned smem_u32(const void* p) {
    return (unsigned)__cvta_generic_to_shared(p);
}
__device__ __forceinline__ void ldsm4(unsigned* r, unsigned addr) {
    asm volatile("ldmatrix.sync.aligned.m8n8.x4.shared.b16 {%0,%1,%2,%3}, [%4];"
        : "=r"(r[0]), "=r"(r[1]), "=r"(r[2]), "=r"(r[3]) : "r"(addr));
}
__device__ __forceinline__ void mma16816(float* d, const unsigned* a,
                                         unsigned b0, unsigned b1) {
    asm volatile("mma.sync.aligned.m16n8k16.row.col.f32.bf16.bf16.f32 "
                 "{%0,%1,%2,%3}, {%4,%5,%6,%7}, {%8,%9}, {%0,%1,%2,%3};"
        : "+f"(d[0]), "+f"(d[1]), "+f"(d[2]), "+f"(d[3])
        : "r"(a[0]), "r"(a[1]), "r"(a[2]), "r"(a[3]), "r"(b0), "r"(b1));
}
__device__ __forceinline__ void cpa16(unsigned dst, const void* src) {
    asm volatile("cp.async.ca.shared.global [%0], [%1], 16;" :: "r"(dst), "l"(src));
}
__device__ __forceinline__ void cpa_commit() {
    asm volatile("cp.async.commit_group;");
}
__device__ __forceinline__ void cpa_wait0() {
    asm volatile("cp.async.wait_group 0;");
}

// ---------------- hypernet small MLPs + FiLM heads ----------------
__global__ void hyper_small(const int* __restrict__ labels,
                            const float* __restrict__ emb,
                            const float* __restrict__ hw1, const float* __restrict__ hb1,
                            const float* __restrict__ hw2, const float* __restrict__ hb2,
                            const float* __restrict__ f1w1, const float* __restrict__ f1b1,
                            const float* __restrict__ f1w2, const float* __restrict__ f1b2,
                            const float* __restrict__ f2w1, const float* __restrict__ f2b1,
                            const float* __restrict__ f2w2, const float* __restrict__ f2b2)
{
    int b = blockIdx.x;
    int t = threadIdx.x;            // 256 threads
    __shared__ float s_cond[D_];
    __shared__ float s_h1[HID];
    __shared__ float s_t[D_];

    if (t < D_) s_cond[t] = emb[(size_t)labels[b] * D_ + t];
    __syncthreads();

    {
        float a = hb1[t];
        #pragma unroll 4
        for (int k = 0; k < D_; k++) a = fmaf(s_cond[k], hw1[k * HID + t], a);
        s_h1[t] = fmaxf(a, 0.f);
    }
    __syncthreads();

    {
        float a = hb2[t];
        #pragma unroll 4
        for (int k = 0; k < HID; k++) a = fmaf(s_h1[k], hw2[k * HID + t], a);
        g_h2[b][t] = fmaxf(a, 0.f);
    }

    if (t < D_) {
        float v = f1b1[t];
        #pragma unroll 4
        for (int k = 0; k < D_; k++) v = fmaf(s_cond[k], f1w1[k * D_ + t], v);
        s_t[t] = fmaxf(v, 0.f);
    }
    __syncthreads();
    if (t < D_) {
        float v = f1b2[t];
        #pragma unroll 4
        for (int k = 0; k < D_; k++) v = fmaf(s_t[k], f1w2[k * D_ + t], v);
        if (t < C_) g_film[0][b][t] = v; else g_film[1][b][t - C_] = v;
    }
    __syncthreads();

    if (t < D_) {
        float v = f2b1[t];
        #pragma unroll 4
        for (int k = 0; k < D_; k++) v = fmaf(s_cond[k], f2w1[k * D_ + t], v);
        s_t[t] = fmaxf(v, 0.f);
    }
    __syncthreads();
    if (t < D_) {
        float v = f2b2[t];
        #pragma unroll 4
        for (int k = 0; k < D_; k++) v = fmaf(s_t[k], f2w2[k * D_ + t], v);
        if (t < C_) g_film[2][b][t] = v; else g_film[3][b][t - C_] = v;
    }
}

// ---------------- big hypernet layer -> bf16 hi/lo weight planes ----------------
__global__ void pack_weights(const float* __restrict__ hw3, const float* __restrict__ hb3)
{
    __shared__ float s_h2t[HID][B_];
    int tid = threadIdx.x;
    for (int it = 0; it < B_; it++)
        s_h2t[tid][it] = g_h2[it][tid];
    __syncthreads();

    size_t j = (size_t)blockIdx.x * 256 + tid;   // j < 147456
    float acc[B_];
    #pragma unroll
    for (int b = 0; b < B_; b++) acc[b] = 0.f;

    const float* col = hw3 + j;
    #pragma unroll 4
    for (int k = 0; k < HID; k++) {
        float w = col[(size_t)k * (2 * TOT1)];
        const float4* v = reinterpret_cast<const float4*>(&s_h2t[k][0]);
        #pragma unroll
        for (int q = 0; q < 8; q++) {
            float4 h = v[q];
            acc[4 * q + 0] = fmaf(w, h.x, acc[4 * q + 0]);
            acc[4 * q + 1] = fmaf(w, h.y, acc[4 * q + 1]);
            acc[4 * q + 2] = fmaf(w, h.z, acc[4 * q + 2]);
            acc[4 * q + 3] = fmaf(w, h.w, acc[4 * q + 3]);
        }
    }

    float bias = hb3[j];
    int which = (j >= TOT1) ? 1 : 0;
    int jj = which ? (int)j - TOT1 : (int)j;
    int co  = jj / 576;
    int rem = jj - co * 576;
    int ci  = rem / 9;
    int tap = rem - ci * 9;
    int cc  = ci >> 4;
    int cl  = ci & 15;
    int didx = ((cc * 9 + tap) * C_ + co) * 16 + cl;
    #pragma unroll
    for (int b = 0; b < B_; b++) {
        float v = acc[b] + bias;
        __nv_bfloat16 h = __float2bfloat16(v);
        __nv_bfloat16 l = __float2bfloat16(v - __bfloat162float(h));
        g_wh[which][b][didx] = h;
        g_wl[which][b][didx] = l;
    }
}

// ---------------- initial state -> bf16 planes ----------------
__global__ void init_convert(const float* __restrict__ init)
{
    int bc = blockIdx.x;                 // b*4+cc
    int b  = bc >> 2, cc = bc & 3;
    int y  = blockIdx.y * 4 + (threadIdx.x >> 6);
    int x  = threadIdx.x & 63;

    __nv_bfloat16 h[16], l[16];
    #pragma unroll
    for (int ci = 0; ci < 16; ci++) {
        float v = init[((size_t)(b * C_ + cc * 16 + ci)) * NPIX + y * HW_ + x];
        h[ci] = __float2bfloat16(v);
        l[ci] = __float2bfloat16(v - __bfloat162float(h[ci]));
    }
    size_t o = ((size_t)bc * NPIX + y * HW_ + x) * 16;
    reinterpret_cast<uint4*>(g_sh + o)[0] = reinterpret_cast<uint4*>(h)[0];
    reinterpret_cast<uint4*>(g_sh + o)[1] = reinterpret_cast<uint4*>(h)[1];
    reinterpret_cast<uint4*>(g_sl + o)[0] = reinterpret_cast<uint4*>(l)[0];
    reinterpret_cast<uint4*>(g_sl + o)[1] = reinterpret_cast<uint4*>(l)[1];
}

// ---------------- conv step: cp.async double-buffered bf16x3 tensor-core conv ----------------
// block: (ytile 0..15, b 0..31), 512 threads = 16 warps.
// Output tile: 4 rows x 64 x = 256 pixels x 64 co.
// warp (wm=wid>>2 row, wn=wid&3 co16-group): m64 (one row) x n16.
// smem per buffer: A [row6][slot66][pitch24] hi+lo; W [tap9][co64][pitch24] hi+lo.
#define PITCHB 48                       // bytes per pitch row (24 bf16)
#define SIN_PLANE_B (6 * 66 * PITCHB)   // 19008 B
#define SW_PLANE_B  (9 * 64 * PITCHB)   // 27648 B
#define BUF_B (2 * SIN_PLANE_B + 2 * SW_PLANE_B)   // 93312 B
#define SMEM_BYTES (2 * BUF_B)                     // 186624 B
#define NCHUNK_IN (6 * 66 * 2 * 2)      // 1584
#define NCHUNK_W  (9 * 64 * 2 * 2)      // 2304
#define NCHUNK    (NCHUNK_IN + NCHUNK_W)

__global__ __launch_bounds__(512, 1)
void conv_step(const float* __restrict__ init,
               const float* __restrict__ blendp,
               float* __restrict__ head,
               float* __restrict__ traj,
               int step, int isB)
{
    extern __shared__ __align__(16) char smem[];
    const unsigned sbase = smem_u32(smem);

    const int tid  = threadIdx.x;
    const int lane = tid & 31;
    const int wid  = tid >> 5;
    const int wm   = wid >> 2;         // output row 0..3
    const int wn   = wid & 3;          // co16 group 0..3
    const int b    = blockIdx.y;
    const int y0   = blockIdx.x * 4;

    const __nv_bfloat16* in_h = isB ? g_uh : g_sh;
    const __nv_bfloat16* in_l = isB ? g_ul : g_sl;
    const __nv_bfloat16* wbh  = &g_wh[isB][b][0];
    const __nv_bfloat16* wbl  = &g_wl[isB][b][0];
    const float* bsrc = (step == 0) ? init : g_X;

    // ldmatrix per-lane offsets
    const int g  = lane >> 3;
    const int r8 = lane & 7;
    unsigned aoff[4];
    #pragma unroll
    for (int t = 0; t < 4; t++)
        aoff[t] = (unsigned)((wm * 66 + t * 16 + (g & 1) * 8 + r8) * PITCHB + (g >> 1) * 16);
    const unsigned boff = (unsigned)((wn * 16 + (g >> 1) * 8 + r8) * PITCHB + (g & 1) * 16);

    float acc[4][2][4];
    #pragma unroll
    for (int t = 0; t < 4; t++)
        #pragma unroll
        for (int n = 0; n < 2; n++)
            #pragma unroll
            for (int k = 0; k < 4; k++) acc[t][n][k] = 0.f;

    // ---- fill(cc, buf): cp.async 16B chunks ----
    auto fill = [&](int cc, int buf) {
        const unsigned base = sbase + buf * BUF_B;
        #pragma unroll
        for (int it = 0; it < 8; it++) {
            int idx = tid + 512 * it;
            if (idx < NCHUNK_IN) {
                int half  = idx & 1;
                int plane = (idx >> 1) & 1;
                int rest  = idx >> 2;          // < 396
                int slot  = rest % 66;
                int row   = rest / 66;
                int gy = (y0 - 1 + row) & 63;
                int gx = (slot + 63) & 63;
                unsigned dst = base + plane * SIN_PLANE_B + (row * 66 + slot) * PITCHB + half * 16;
                const __nv_bfloat16* src =
                    (plane ? in_l : in_h) +
                    (((size_t)(b * 4 + cc) * NPIX + gy * HW_ + gx) * 16 + half * 8);
                cpa16(dst, src);
            } else if (idx < NCHUNK) {
                int c = idx - NCHUNK_IN;
                int half  = c & 1;
                int plane = (c >> 1) & 1;
                int rest  = c >> 2;            // < 576
                int co  = rest & 63;
                int tap = rest >> 6;
                unsigned dst = base + 2 * SIN_PLANE_B + plane * SW_PLANE_B +
                               (tap * 64 + co) * PITCHB + half * 16;
                const __nv_bfloat16* src =
                    (plane ? wbl : wbh) + (((cc * 9 + tap) * 64 + co) * 16 + half * 8);
                cpa16(dst, src);
            }
        }
    };

    fill(0, 0);
    cpa_commit();

    for (int cc = 0; cc < 4; cc++) {
        cpa_wait0();
        __syncthreads();
        if (cc < 3) {
            fill(cc + 1, (cc + 1) & 1);
            cpa_commit();
        }
        const unsigned bb   = sbase + (cc & 1) * BUF_B;
        const unsigned u_ih = bb;
        const unsigned u_il = bb + SIN_PLANE_B;
        const unsigned u_wh = bb + 2 * SIN_PLANE_B;
        const unsigned u_wl = bb + 2 * SIN_PLANE_B + SW_PLANE_B;

        #pragma unroll
        for (int tap = 0; tap < 9; tap++) {
            const int dy = tap / 3, dx = tap % 3;
            const unsigned ta = (unsigned)((dy * 66 + dx) * PITCHB);
            const unsigned tb = (unsigned)(tap * 64 * PITCHB);

            unsigned bh[4], bl[4];
            ldsm4(bh, u_wh + boff + tb);
            ldsm4(bl, u_wl + boff + tb);

            #pragma unroll
            for (int t = 0; t < 4; t++) {
                unsigned ah[4], al[4];
                ldsm4(ah, u_ih + aoff[t] + ta);
                ldsm4(al, u_il + aoff[t] + ta);
                // hi*hi
                mma16816(acc[t][0], ah, bh[0], bh[1]);
                mma16816(acc[t][1], ah, bh[2], bh[3]);
                // hi*lo(w)
                mma16816(acc[t][0], ah, bl[0], bl[1]);
                mma16816(acc[t][1], ah, bl[2], bl[3]);
                // lo(a)*hi
                mma16816(acc[t][0], al, bh[0], bh[1]);
                mma16816(acc[t][1], al, bh[2], bh[3]);
            }
        }
        if (cc < 3) __syncthreads();
    }

    // ---------------- epilogue ----------------
    float s = 0.f, oms = 1.f;
    if (isB) {
        s = 1.f / (1.f + expf(-blendp[0]));
        oms = 1.f - s;
    }
    const int y = y0 + wm;
    const int rbase = lane >> 2;
    const int cpair = (lane & 3) * 2;

    __nv_bfloat16* out_h = isB ? g_sh : g_uh;
    __nv_bfloat16* out_l = isB ? g_sl : g_ul;

    #pragma unroll
    for (int t = 0; t < 4; t++) {
        #pragma unroll
        for (int half = 0; half < 2; half++) {
            int px = t * 16 + rbase + 8 * half;
            #pragma unroll
            for (int n = 0; n < 2; n++) {
                int cl0 = n * 8 + cpair;
                int co0 = wn * 16 + cl0;
                float v0, v1;
                {
                    float gv0 = g_film[isB * 2][b][co0];
                    float bv0 = g_film[isB * 2 + 1][b][co0];
                    float gv1 = g_film[isB * 2][b][co0 + 1];
                    float bv1 = g_film[isB * 2 + 1][b][co0 + 1];
                    v0 = fmaxf(fmaf(gv0, acc[t][n][2 * half + 0], bv0), 0.f);
                    v1 = fmaxf(fmaf(gv1, acc[t][n][2 * half + 1], bv1), 0.f);
                }
                if (isB) {
                    size_t o0 = ((size_t)(b * C_ + co0)) * NPIX + (size_t)y * HW_ + px;
                    size_t o1 = o0 + NPIX;
                    float ng0 = fmaf(oms, bsrc[o0], s * v0);
                    float ng1 = fmaf(oms, bsrc[o1], s * v1);
                    g_X[o0] = ng0;
                    g_X[o1] = ng1;
                    v0 = ng0; v1 = ng1;
                    if (co0 < 3) {
                        float r0 = 1.f / (1.f + expf(-ng0));
                        traj[(((size_t)step * B_ + b) * 3 + co0) * NPIX + (size_t)y * HW_ + px] = r0;
                        if (step == NSTEP - 1)
                            head[((size_t)(b * 3 + co0)) * NPIX + (size_t)y * HW_ + px] = r0;
                        if (co0 + 1 < 3) {
                            float r1 = 1.f / (1.f + expf(-ng1));
                            traj[(((size_t)step * B_ + b) * 3 + co0 + 1) * NPIX + (size_t)y * HW_ + px] = r1;
                            if (step == NSTEP - 1)
                                head[((size_t)(b * 3 + co0 + 1)) * NPIX + (size_t)y * HW_ + px] = r1;
                        }
                    }
                }
                // split to bf16 hi/lo planes (next conv's input)
                __nv_bfloat16 h0 = __float2bfloat16(v0);
                __nv_bfloat16 l0 = __float2bfloat16(v0 - __bfloat162float(h0));
                __nv_bfloat16 h1 = __float2bfloat16(v1);
                __nv_bfloat16 l1 = __float2bfloat16(v1 - __bfloat162float(h1));
                size_t po = ((size_t)(b * 4 + wn) * NPIX + (size_t)y * HW_ + px) * 16 + cl0;
                __nv_bfloat162 hp; hp.x = h0; hp.y = h1;
                __nv_bfloat162 lp; lp.x = l0; lp.y = l1;
                *reinterpret_cast<__nv_bfloat162*>(out_h + po) = hp;
                *reinterpret_cast<__nv_bfloat162*>(out_l + po) = lp;
            }
        }
    }
}

// ---------------- launcher ----------------
extern "C" void kernel_launch(void* const* d_in, const int* in_sizes, int n_in,
                              void* d_out, int out_size)
{
    const int*   labels = (const int*)  d_in[0];
    const float* init   = (const float*)d_in[1];
    const float* emb    = (const float*)d_in[2];
    const float* hw1    = (const float*)d_in[3];
    const float* hb1    = (const float*)d_in[4];
    const float* hw2    = (const float*)d_in[5];
    const float* hb2    = (const float*)d_in[6];
    const float* hw3    = (const float*)d_in[7];
    const float* hb3    = (const float*)d_in[8];
    const float* f1w1   = (const float*)d_in[9];
    const float* f1b1   = (const float*)d_in[10];
    const float* f1w2   = (const float*)d_in[11];
    const float* f1b2   = (const float*)d_in[12];
    const float* f2w1   = (const float*)d_in[13];
    const float* f2b1   = (const float*)d_in[14];
    const float* f2w2   = (const float*)d_in[15];
    const float* f2b2   = (const float*)d_in[16];
    const float* blend  = (const float*)d_in[17];

    float* out  = (float*)d_out;
    float* head = out;                              // traj[-1]: [B,3,H,W]
    float* traj = out + (size_t)B_ * 3 * NPIX;      // traj:     [T,B,3,H,W]

    cudaFuncSetAttribute(conv_step, cudaFuncAttributeMaxDynamicSharedMemorySize, SMEM_BYTES);

    hyper_small<<<B_, 256>>>(labels, emb, hw1, hb1, hw2, hb2,
                             f1w1, f1b1, f1w2, f1b2, f2w1, f2b1, f2w2, f2b2);
    pack_weights<<<(2 * TOT1) / 256, 256>>>(hw3, hb3);
    init_convert<<<dim3(B_ * 4, 16), 256>>>(init);

    for (int t = 0; t < NSTEP; t++) {
        conv_step<<<dim3(16, B_), 512, SMEM_BYTES>>>(init, blend, head, traj, t, 0);
        conv_step<<<dim3(16, B_), 512, SMEM_BYTES>>>(init, blend, head, traj, t, 1);
    }
}

// round 5
// speedup vs baseline: 2.2868x; 1.0053x over previous
#include <cuda_runtime.h>
#include <cuda_bf16.h>
#include <math.h>

// ---------------- problem constants ----------------
#define B_  32
#define C_  64
#define D_  128
#define HID 256
#define HW_ 64
#define NPIX 4096
#define TOT1 36864
#define NSTEP 32

// ---------------- device scratch ----------------
__device__ float g_h2[B_][HID];
__device__ float g_film[4][B_][C_];   // g1, be1, g2, be2
// bf16 hi/lo weight planes: [which][b][cc(4)][tap(9)][co(64)][ci16]
__device__ __nv_bfloat16 g_wh[2][B_][4 * 9 * C_ * 16];
__device__ __nv_bfloat16 g_wl[2][B_][4 * 9 * C_ * 16];
// activation planes: [b][cc(4)][y][x][ci16]
__device__ __nv_bfloat16 g_sh[(size_t)B_ * 4 * NPIX * 16];  // state (hi)
__device__ __nv_bfloat16 g_sl[(size_t)B_ * 4 * NPIX * 16];  // state (lo)
__device__ __nv_bfloat16 g_uh[(size_t)B_ * 4 * NPIX * 16];  // intermediate (hi)
__device__ __nv_bfloat16 g_ul[(size_t)B_ * 4 * NPIX * 16];  // intermediate (lo)
__device__ float g_X[(size_t)B_ * C_ * NPIX];               // f32 state (blend source), NCHW

// ---------------- PTX helpers ----------------
__device__ __forceinline__ unsigned smem_u32(const void* p) {
    return (unsigned)__cvta_generic_to_shared(p);
}
__device__ __forceinline__ void ldsm4(unsigned* r, unsigned addr) {
    asm volatile("ldmatrix.sync.aligned.m8n8.x4.shared.b16 {%0,%1,%2,%3}, [%4];"
        : "=r"(r[0]), "=r"(r[1]), "=r"(r[2]), "=r"(r[3]) : "r"(addr));
}
__device__ __forceinline__ void mma16816(float* d, const unsigned* a,
                                         unsigned b0, unsigned b1) {
    asm volatile("mma.sync.aligned.m16n8k16.row.col.f32.bf16.bf16.f32 "
                 "{%0,%1,%2,%3}, {%4,%5,%6,%7}, {%8,%9}, {%0,%1,%2,%3};"
        : "+f"(d[0]), "+f"(d[1]), "+f"(d[2]), "+f"(d[3])
        : "r"(a[0]), "r"(a[1]), "r"(a[2]), "r"(a[3]), "r"(b0), "r"(b1));
}
__device__ __forceinline__ void cpa16(unsigned dst, const void* src) {
    asm volatile("cp.async.ca.shared.global [%0], [%1], 16;" :: "r"(dst), "l"(src));
}
__device__ __forceinline__ void cpa_commit() {
    asm volatile("cp.async.commit_group;");
}
__device__ __forceinline__ void cpa_wait0() {
    asm volatile("cp.async.wait_group 0;");
}

// ---------------- hypernet small MLPs + FiLM heads ----------------
__global__ void hyper_small(const int* __restrict__ labels,
                            const float* __restrict__ emb,
                            const float* __restrict__ hw1, const float* __restrict__ hb1,
                            const float* __restrict__ hw2, const float* __restrict__ hb2,
                            const float* __restrict__ f1w1, const float* __restrict__ f1b1,
                            const float* __restrict__ f1w2, const float* __restrict__ f1b2,
                            const float* __restrict__ f2w1, const float* __restrict__ f2b1,
                            const float* __restrict__ f2w2, const float* __restrict__ f2b2)
{
    int b = blockIdx.x;
    int t = threadIdx.x;            // 256 threads
    __shared__ float s_cond[D_];
    __shared__ float s_h1[HID];
    __shared__ float s_t[D_];

    if (t < D_) s_cond[t] = emb[(size_t)labels[b] * D_ + t];
    __syncthreads();

    {
        float a = hb1[t];
        #pragma unroll 4
        for (int k = 0; k < D_; k++) a = fmaf(s_cond[k], hw1[k * HID + t], a);
        s_h1[t] = fmaxf(a, 0.f);
    }
    __syncthreads();

    {
        float a = hb2[t];
        #pragma unroll 4
        for (int k = 0; k < HID; k++) a = fmaf(s_h1[k], hw2[k * HID + t], a);
        g_h2[b][t] = fmaxf(a, 0.f);
    }

    if (t < D_) {
        float v = f1b1[t];
        #pragma unroll 4
        for (int k = 0; k < D_; k++) v = fmaf(s_cond[k], f1w1[k * D_ + t], v);
        s_t[t] = fmaxf(v, 0.f);
    }
    __syncthreads();
    if (t < D_) {
        float v = f1b2[t];
        #pragma unroll 4
        for (int k = 0; k < D_; k++) v = fmaf(s_t[k], f1w2[k * D_ + t], v);
        if (t < C_) g_film[0][b][t] = v; else g_film[1][b][t - C_] = v;
    }
    __syncthreads();

    if (t < D_) {
        float v = f2b1[t];
        #pragma unroll 4
        for (int k = 0; k < D_; k++) v = fmaf(s_cond[k], f2w1[k * D_ + t], v);
        s_t[t] = fmaxf(v, 0.f);
    }
    __syncthreads();
    if (t < D_) {
        float v = f2b2[t];
        #pragma unroll 4
        for (int k = 0; k < D_; k++) v = fmaf(s_t[k], f2w2[k * D_ + t], v);
        if (t < C_) g_film[2][b][t] = v; else g_film[3][b][t - C_] = v;
    }
}

// ---------------- big hypernet layer -> bf16 hi/lo weight planes ----------------
__global__ void pack_weights(const float* __restrict__ hw3, const float* __restrict__ hb3)
{
    __shared__ float s_h2t[HID][B_];
    int tid = threadIdx.x;
    for (int it = 0; it < B_; it++)
        s_h2t[tid][it] = g_h2[it][tid];
    __syncthreads();

    size_t j = (size_t)blockIdx.x * 256 + tid;   // j < 147456
    float acc[B_];
    #pragma unroll
    for (int b = 0; b < B_; b++) acc[b] = 0.f;

    const float* col = hw3 + j;
    #pragma unroll 4
    for (int k = 0; k < HID; k++) {
        float w = col[(size_t)k * (2 * TOT1)];
        const float4* v = reinterpret_cast<const float4*>(&s_h2t[k][0]);
        #pragma unroll
        for (int q = 0; q < 8; q++) {
            float4 h = v[q];
            acc[4 * q + 0] = fmaf(w, h.x, acc[4 * q + 0]);
            acc[4 * q + 1] = fmaf(w, h.y, acc[4 * q + 1]);
            acc[4 * q + 2] = fmaf(w, h.z, acc[4 * q + 2]);
            acc[4 * q + 3] = fmaf(w, h.w, acc[4 * q + 3]);
        }
    }

    float bias = hb3[j];
    int which = (j >= TOT1) ? 1 : 0;
    int jj = which ? (int)j - TOT1 : (int)j;
    int co  = jj / 576;
    int rem = jj - co * 576;
    int ci  = rem / 9;
    int tap = rem - ci * 9;
    int cc  = ci >> 4;
    int cl  = ci & 15;
    int didx = ((cc * 9 + tap) * C_ + co) * 16 + cl;
    #pragma unroll
    for (int b = 0; b < B_; b++) {
        float v = acc[b] + bias;
        __nv_bfloat16 h = __float2bfloat16(v);
        __nv_bfloat16 l = __float2bfloat16(v - __bfloat162float(h));
        g_wh[which][b][didx] = h;
        g_wl[which][b][didx] = l;
    }
}

// ---------------- initial state -> bf16 planes ----------------
__global__ void init_convert(const float* __restrict__ init)
{
    int bc = blockIdx.x;                 // b*4+cc
    int b  = bc >> 2, cc = bc & 3;
    int y  = blockIdx.y * 4 + (threadIdx.x >> 6);
    int x  = threadIdx.x & 63;

    __nv_bfloat16 h[16], l[16];
    #pragma unroll
    for (int ci = 0; ci < 16; ci++) {
        float v = init[((size_t)(b * C_ + cc * 16 + ci)) * NPIX + y * HW_ + x];
        h[ci] = __float2bfloat16(v);
        l[ci] = __float2bfloat16(v - __bfloat162float(h[ci]));
    }
    size_t o = ((size_t)bc * NPIX + y * HW_ + x) * 16;
    reinterpret_cast<uint4*>(g_sh + o)[0] = reinterpret_cast<uint4*>(h)[0];
    reinterpret_cast<uint4*>(g_sh + o)[1] = reinterpret_cast<uint4*>(h)[1];
    reinterpret_cast<uint4*>(g_sl + o)[0] = reinterpret_cast<uint4*>(l)[0];
    reinterpret_cast<uint4*>(g_sl + o)[1] = reinterpret_cast<uint4*>(l)[1];
}

// ---------------- conv step: cp.async double-buffered bf16x3 tensor-core conv ----------------
// block: (ytile 0..15, b 0..31), 512 threads = 16 warps.
// Output tile: 4 rows x 64 x = 256 pixels x 64 co.
// warp (wm=wid>>2 row, wn=wid&3 co16-group): m64 (one row) x n16.
// smem per buffer: A [row6][slot66][pitch24] hi+lo; W [tap9][co64][pitch24] hi+lo.
#define PITCHB 48                       // bytes per pitch row (24 bf16)
#define SIN_PLANE_B (6 * 66 * PITCHB)   // 19008 B
#define SW_PLANE_B  (9 * 64 * PITCHB)   // 27648 B
#define BUF_B (2 * SIN_PLANE_B + 2 * SW_PLANE_B)   // 93312 B
#define SMEM_BYTES (2 * BUF_B)                     // 186624 B
#define NCHUNK_IN (6 * 66 * 2 * 2)      // 1584
#define NCHUNK_W  (9 * 64 * 2 * 2)      // 2304
#define NCHUNK    (NCHUNK_IN + NCHUNK_W)

__global__ __launch_bounds__(512, 1)
void conv_step(const float* __restrict__ init,
               const float* __restrict__ blendp,
               float* __restrict__ head,
               float* __restrict__ traj,
               int step, int isB)
{
    extern __shared__ __align__(16) char smem[];
    const unsigned sbase = smem_u32(smem);

    const int tid  = threadIdx.x;
    const int lane = tid & 31;
    const int wid  = tid >> 5;
    const int wm   = wid >> 2;         // output row 0..3
    const int wn   = wid & 3;          // co16 group 0..3
    const int b    = blockIdx.y;
    const int y0   = blockIdx.x * 4;

    const __nv_bfloat16* in_h = isB ? g_uh : g_sh;
    const __nv_bfloat16* in_l = isB ? g_ul : g_sl;
    const __nv_bfloat16* wbh  = &g_wh[isB][b][0];
    const __nv_bfloat16* wbl  = &g_wl[isB][b][0];
    const float* bsrc = (step == 0) ? init : g_X;

    // ldmatrix per-lane offsets
    const int g  = lane >> 3;
    const int r8 = lane & 7;
    unsigned aoff[4];
    #pragma unroll
    for (int t = 0; t < 4; t++)
        aoff[t] = (unsigned)((wm * 66 + t * 16 + (g & 1) * 8 + r8) * PITCHB + (g >> 1) * 16);
    const unsigned boff = (unsigned)((wn * 16 + (g >> 1) * 8 + r8) * PITCHB + (g & 1) * 16);

    float acc[4][2][4];
    #pragma unroll
    for (int t = 0; t < 4; t++)
        #pragma unroll
        for (int n = 0; n < 2; n++)
            #pragma unroll
            for (int k = 0; k < 4; k++) acc[t][n][k] = 0.f;

    // ---- fill(cc, buf): cp.async 16B chunks ----
    auto fill = [&](int cc, int buf) {
        const unsigned base = sbase + buf * BUF_B;
        #pragma unroll
        for (int it = 0; it < 8; it++) {
            int idx = tid + 512 * it;
            if (idx < NCHUNK_IN) {
                int half  = idx & 1;
                int plane = (idx >> 1) & 1;
                int rest  = idx >> 2;          // < 396
                int slot  = rest % 66;
                int row   = rest / 66;
                int gy = (y0 - 1 + row) & 63;
                int gx = (slot + 63) & 63;
                unsigned dst = base + plane * SIN_PLANE_B + (row * 66 + slot) * PITCHB + half * 16;
                const __nv_bfloat16* src =
                    (plane ? in_l : in_h) +
                    (((size_t)(b * 4 + cc) * NPIX + gy * HW_ + gx) * 16 + half * 8);
                cpa16(dst, src);
            } else if (idx < NCHUNK) {
                int c = idx - NCHUNK_IN;
                int half  = c & 1;
                int plane = (c >> 1) & 1;
                int rest  = c >> 2;            // < 576
                int co  = rest & 63;
                int tap = rest >> 6;
                unsigned dst = base + 2 * SIN_PLANE_B + plane * SW_PLANE_B +
                               (tap * 64 + co) * PITCHB + half * 16;
                const __nv_bfloat16* src =
                    (plane ? wbl : wbh) + (((cc * 9 + tap) * 64 + co) * 16 + half * 8);
                cpa16(dst, src);
            }
        }
    };

    fill(0, 0);
    cpa_commit();

    for (int cc = 0; cc < 4; cc++) {
        cpa_wait0();
        __syncthreads();
        if (cc < 3) {
            fill(cc + 1, (cc + 1) & 1);
            cpa_commit();
        }
        const unsigned bb   = sbase + (cc & 1) * BUF_B;
        const unsigned u_ih = bb;
        const unsigned u_il = bb + SIN_PLANE_B;
        const unsigned u_wh = bb + 2 * SIN_PLANE_B;
        const unsigned u_wl = bb + 2 * SIN_PLANE_B + SW_PLANE_B;

        #pragma unroll
        for (int tap = 0; tap < 9; tap++) {
            const int dy = tap / 3, dx = tap % 3;
            const unsigned ta = (unsigned)((dy * 66 + dx) * PITCHB);
            const unsigned tb = (unsigned)(tap * 64 * PITCHB);

            unsigned bh[4], bl[4];
            ldsm4(bh, u_wh + boff + tb);
            ldsm4(bl, u_wl + boff + tb);

            #pragma unroll
            for (int t = 0; t < 4; t++) {
                unsigned ah[4], al[4];
                ldsm4(ah, u_ih + aoff[t] + ta);
                ldsm4(al, u_il + aoff[t] + ta);
                // hi*hi
                mma16816(acc[t][0], ah, bh[0], bh[1]);
                mma16816(acc[t][1], ah, bh[2], bh[3]);
                // hi*lo(w)
                mma16816(acc[t][0], ah, bl[0], bl[1]);
                mma16816(acc[t][1], ah, bl[2], bl[3]);
                // lo(a)*hi
                mma16816(acc[t][0], al, bh[0], bh[1]);
                mma16816(acc[t][1], al, bh[2], bh[3]);
            }
        }
        if (cc < 3) __syncthreads();
    }

    // ---------------- epilogue ----------------
    float s = 0.f, oms = 1.f;
    if (isB) {
        s = 1.f / (1.f + expf(-blendp[0]));
        oms = 1.f - s;
    }
    const int y = y0 + wm;
    const int rbase = lane >> 2;
    const int cpair = (lane & 3) * 2;

    __nv_bfloat16* out_h = isB ? g_sh : g_uh;
    __nv_bfloat16* out_l = isB ? g_sl : g_ul;

    #pragma unroll
    for (int t = 0; t < 4; t++) {
        #pragma unroll
        for (int half = 0; half < 2; half++) {
            int px = t * 16 + rbase + 8 * half;
            #pragma unroll
            for (int n = 0; n < 2; n++) {
                int cl0 = n * 8 + cpair;
                int co0 = wn * 16 + cl0;
                float v0, v1;
                {
                    float gv0 = g_film[isB * 2][b][co0];
                    float bv0 = g_film[isB * 2 + 1][b][co0];
                    float gv1 = g_film[isB * 2][b][co0 + 1];
                    float bv1 = g_film[isB * 2 + 1][b][co0 + 1];
                    v0 = fmaxf(fmaf(gv0, acc[t][n][2 * half + 0], bv0), 0.f);
                    v1 = fmaxf(fmaf(gv1, acc[t][n][2 * half + 1], bv1), 0.f);
                }
                if (isB) {
                    size_t o0 = ((size_t)(b * C_ + co0)) * NPIX + (size_t)y * HW_ + px;
                    size_t o1 = o0 + NPIX;
                    float ng0 = fmaf(oms, bsrc[o0], s * v0);
                    float ng1 = fmaf(oms, bsrc[o1], s * v1);
                    g_X[o0] = ng0;
                    g_X[o1] = ng1;
                    v0 = ng0; v1 = ng1;
                    if (co0 < 3) {
                        float r0 = 1.f / (1.f + expf(-ng0));
                        traj[(((size_t)step * B_ + b) * 3 + co0) * NPIX + (size_t)y * HW_ + px] = r0;
                        if (step == NSTEP - 1)
                            head[((size_t)(b * 3 + co0)) * NPIX + (size_t)y * HW_ + px] = r0;
                        if (co0 + 1 < 3) {
                            float r1 = 1.f / (1.f + expf(-ng1));
                            traj[(((size_t)step * B_ + b) * 3 + co0 + 1) * NPIX + (size_t)y * HW_ + px] = r1;
                            if (step == NSTEP - 1)
                                head[((size_t)(b * 3 + co0 + 1)) * NPIX + (size_t)y * HW_ + px] = r1;
                        }
                    }
                }
                // split to bf16 hi/lo planes (next conv's input)
                __nv_bfloat16 h0 = __float2bfloat16(v0);
                __nv_bfloat16 l0 = __float2bfloat16(v0 - __bfloat162float(h0));
                __nv_bfloat16 h1 = __float2bfloat16(v1);
                __nv_bfloat16 l1 = __float2bfloat16(v1 - __bfloat162float(h1));
                size_t po = ((size_t)(b * 4 + wn) * NPIX + (size_t)y * HW_ + px) * 16 + cl0;
                __nv_bfloat162 hp; hp.x = h0; hp.y = h1;
                __nv_bfloat162 lp; lp.x = l0; lp.y = l1;
                *reinterpret_cast<__nv_bfloat162*>(out_h + po) = hp;
                *reinterpret_cast<__nv_bfloat162*>(out_l + po) = lp;
            }
        }
    }
}

// ---------------- launcher ----------------
extern "C" void kernel_launch(void* const* d_in, const int* in_sizes, int n_in,
                              void* d_out, int out_size)
{
    const int*   labels = (const int*)  d_in[0];
    const float* init   = (const float*)d_in[1];
    const float* emb    = (const float*)d_in[2];
    const float* hw1    = (const float*)d_in[3];
    const float* hb1    = (const float*)d_in[4];
    const float* hw2    = (const float*)d_in[5];
    const float* hb2    = (const float*)d_in[6];
    const float* hw3    = (const float*)d_in[7];
    const float* hb3    = (const float*)d_in[8];
    const float* f1w1   = (const float*)d_in[9];
    const float* f1b1   = (const float*)d_in[10];
    const float* f1w2   = (const float*)d_in[11];
    const float* f1b2   = (const float*)d_in[12];
    const float* f2w1   = (const float*)d_in[13];
    const float* f2b1   = (const float*)d_in[14];
    const float* f2w2   = (const float*)d_in[15];
    const float* f2b2   = (const float*)d_in[16];
    const float* blend  = (const float*)d_in[17];

    float* out  = (float*)d_out;
    float* head = out;                              // traj[-1]: [B,3,H,W]
    float* traj = out + (size_t)B_ * 3 * NPIX;      // traj:     [T,B,3,H,W]

    cudaFuncSetAttribute(conv_step, cudaFuncAttributeMaxDynamicSharedMemorySize, SMEM_BYTES);

    hyper_small<<<B_, 256>>>(labels, emb, hw1, hb1, hw2, hb2,
                             f1w1, f1b1, f1w2, f1b2, f2w1, f2b1, f2w2, f2b2);
    pack_weights<<<(2 * TOT1) / 256, 256>>>(hw3, hb3);
    init_convert<<<dim3(B_ * 4, 16), 256>>>(init);

    for (int t = 0; t < NSTEP; t++) {
        conv_step<<<dim3(16, B_), 512, SMEM_BYTES>>>(init, blend, head, traj, t, 0);
        conv_step<<<dim3(16, B_), 512, SMEM_BYTES>>>(init, blend, head, traj, t, 1);
    }
}